// round 5
// baseline (speedup 1.0000x reference)
#include <cuda_runtime.h>
#include <math.h>
#include <cstdint>

#define N    3072
#define NT   256
#define NWP  8        // warps per block
#define KMAX 12       // ceil((N-1)/NT)

#define ANGLE_THR_BITS 0x3FC90FDB   // f32(pi/2)

// Precomputed pairwise distance matrix (bit-exact ref 'dists'), 37.7MB.
__device__ float g_dmat[(size_t)N * N];

struct Smem {
    float px[N], py[N], pz[N];     // points (px reused as sort keys later)
    int   slbl[N];                 // per-point class
    int   sdl[N];                  // per-point cluster label
    float ccx[N], ccy[N], ccz[N];  // per-cluster centres
    int   ccount[N], ccls[N];      // per-cluster size / class
    int   order[N];                // scan phase: member list of current cluster
    int   items[N];                // scan phase: unvisited packed list (idx | lbl<<12)
    int   remap[N];                // scan phase: posOf[idx] -> position in items
    unsigned char keep[N];
    float rmin[NWP], rmax[NWP];
    unsigned long long rpack[NWP];
    float amdxy[10], amdz[10], ar2[10];
    int   clsCount[10], clsBase[11];
    int   bnc;
    float bval; unsigned ordb; int flag0;   // angle threshold data
};

__device__ __forceinline__ float norm3_xla(float x, float y, float z) {
    float s = __fadd_rn(__fadd_rn(__fmul_rn(x, x), __fmul_rn(y, y)), __fmul_rn(z, z));
    return __fsqrt_rn(s);
}
// XLA acos lowering: 2*atan2(sqrt(1-x*x), 1+x); pi at x==-1. Same libdevice atan2f
// as the reference -> bit-identical.
__device__ __forceinline__ float acos_xla(float x) {
    float s = __fsqrt_rn(__fsub_rn(1.0f, __fmul_rn(x, x)));
    float r = 2.0f * atan2f(s, __fadd_rn(1.0f, x));
    if (x == -1.0f) r = __int_as_float(0x40490FDB);
    return r;
}
__device__ __forceinline__ unsigned ford(float f) {          // float -> ordered uint
    unsigned u = __float_as_uint(f);
    return (u & 0x80000000u) ? ~u : (u | 0x80000000u);
}
__device__ __forceinline__ float ford_inv(unsigned o) {
    unsigned u = (o & 0x80000000u) ? (o ^ 0x80000000u) : ~o;
    return __uint_as_float(u);
}

__global__ void dist_kernel(const float* __restrict__ pts) {
    int i = blockIdx.x;
    float ax = pts[3*i], ay = pts[3*i+1], az = pts[3*i+2];
    float* row = g_dmat + (size_t)i * N;
    for (int j = threadIdx.x; j < N; j += blockDim.x) {
        float dx = __fsub_rn(pts[3*j],   ax);
        float dy = __fsub_rn(pts[3*j+1], ay);
        float dz = __fsub_rn(pts[3*j+2], az);
        row[j] = norm3_xla(dx, dy, dz);
    }
}

__global__ void __launch_bounds__(NT, 1)
frustum_cluster_kernel(const float* __restrict__ pts,
                       const int*   __restrict__ lbl,
                       const float* __restrict__ anchors,
                       float* __restrict__ out)
{
    extern __shared__ char raw[];
    Smem& S = *reinterpret_cast<Smem*>(raw);

    const int tid  = threadIdx.x;
    const int wid  = tid >> 5;
    const int lane = tid & 31;
    const float INF = __int_as_float(0x7f800000);
    const float THR = __int_as_float(ANGLE_THR_BITS);

    // ---------------- init ----------------
    for (int j = tid; j < N; j += NT) {
        S.px[j]   = pts[3*j + 0];
        S.py[j]   = pts[3*j + 1];
        S.pz[j]   = pts[3*j + 2];
        S.slbl[j] = lbl[j];
    }
    // unvisited list excludes point 0
    for (int j = tid; j < N; j += NT) {
        if (j >= 1) {
            S.items[j - 1] = j | (lbl[j] << 12);
            S.remap[j]     = j - 1;            // posOf
        }
    }
    if (tid < 10) {
        float l = anchors[tid*3+0], w = anchors[tid*3+1], h = anchors[tid*3+2];
        S.amdxy[tid] = fmaxf(l, w);
        S.amdz[tid]  = h;
        S.ar2[tid]   = __fdiv_rn(norm3_xla(l, w, h), 2.0f);
    }
    if (tid == 0) {
        S.sdl[0]  = 0;
        S.ccls[0] = lbl[0];
        S.order[0] = 0;                        // member list = {0}
        // binary search for angle threshold: largest x with acos_xla(x) >= THR
        unsigned lo = ford(-1.0f), hi = ford(1.0f);
        while (hi - lo > 1u) {
            unsigned mid = lo + ((hi - lo) >> 1);
            float xm = ford_inv(mid);
            if (acos_xla(xm) >= THR) lo = mid; else hi = mid;
        }
        S.bval  = ford_inv(lo);
        S.ordb  = lo;
        S.flag0 = (acos_xla(0.0f) < THR) ? 1 : 0;
    }
    __syncthreads();

    // all-thread scan state (registers, kept consistent redundantly)
    int m   = N - 1;
    int cur = 0;
    int cls = S.slbl[0];

    // warp-0-only cluster state
    int    lab = 0, cnt = 1, mcnt = 1;
    double sx = 0.0, sy = 0.0, sz = 0.0;
    float  bvalر_unused = 0.f; (void)bvalر_unused;
    float  bvalr = S.bval; unsigned ordbr = S.ordb; int flag0r = S.flag0;
    if (wid == 0) { sx = (double)S.px[0]; sy = (double)S.py[0]; sz = (double)S.pz[0]; }

    float dreg[KMAX];
    int   jreg[KMAX];

    // ---------------- greedy scan: N-1 dependent steps, 2 barriers/step --------
    while (m > 0) {
        const float* __restrict__ drow = g_dmat + (size_t)cur * N;

        // warp 0: angle pass over current cluster members (+ its angle verdict)
        bool angflag = false;
        float wcx = 0.f, wcy = 0.f, wcz = 0.f;
        if (wid == 0) {
            wcx = S.px[cur]; wcy = S.py[cur]; wcz = S.pz[cur];
            float pn = norm3_xla(wcx, wcy, wcz);
            float xm = INF;
            for (int i = lane; i < mcnt; i += 32) {
                int j = S.order[i];
                float dx = __fsub_rn(S.px[j], wcx);
                float dy = __fsub_rn(S.py[j], wcy);
                float dz = __fsub_rn(S.pz[j], wcz);
                float dd = drow[j];
                float dt = -(__fadd_rn(__fadd_rn(__fmul_rn(wcx,dx), __fmul_rn(wcy,dy)),
                                       __fmul_rn(wcz,dz)));
                float den = __fadd_rn(__fmul_rn(pn, dd), 1e-8f);
                xm = fminf(xm, __fdiv_rn(dt, den));
            }
#pragma unroll
            for (int o = 16; o > 0; o >>= 1)
                xm = fminf(xm, __shfl_xor_sync(0xffffffffu, xm, o));
            float xc = fminf(fmaxf(xm, -1.0f), 1.0f);
            if (xc == 0.0f) {
                angflag = (flag0r != 0);
            } else {
                long dlt = (long)ford(xc) - (long)ordbr;
                if (dlt > -65536 && dlt < 65536) angflag = (acos_xla(xc) < THR);
                else                             angflag = (xc > bvalr);
            }
        }

        // pass 1: gather dists over unvisited, min/max
        float lmin = INF, lmax = -INF;
#pragma unroll
        for (int k = 0; k < KMAX; ++k) {
            int pos = tid + (k << 8);
            if (pos < m) {
                int pk = S.items[pos];
                float dd = __ldg(drow + (pk & 0xFFF));
                dreg[k] = dd; jreg[k] = pk;
                lmin = fminf(lmin, dd);
                lmax = fmaxf(lmax, dd);
            }
        }
#pragma unroll
        for (int o = 16; o > 0; o >>= 1) {
            lmin = fminf(lmin, __shfl_xor_sync(0xffffffffu, lmin, o));
            lmax = fmaxf(lmax, __shfl_xor_sync(0xffffffffu, lmax, o));
        }
        if (lane == 0) { S.rmin[wid] = lmin; S.rmax[wid] = lmax; }
        __syncthreads();                                   // barrier 1

        // every warp re-reduces the 8 partials (this IS the broadcast)
        float a = (lane < NWP) ? S.rmin[lane] : INF;
        float b = (lane < NWP) ? S.rmax[lane] : -INF;
#pragma unroll
        for (int o = 4; o > 0; o >>= 1) {
            a = fminf(a, __shfl_xor_sync(0xffffffffu, a, o));
            b = fmaxf(b, __shfl_xor_sync(0xffffffffu, b, o));
        }
        float dmin = __shfl_sync(0xffffffffu, a, 0);
        float dmax = __shfl_sync(0xffffffffu, b, 0);
        float Dn   = __fadd_rn(__fsub_rn(dmax, dmin), 1e-8f);

        // pass 2: argmin of exact normalized cost
        unsigned long long best = 0xFFFFFFFFFFFFFFFFull;
#pragma unroll
        for (int k = 0; k < KMAX; ++k) {
            int pos = tid + (k << 8);
            if (pos < m) {
                float lcost = ((jreg[k] >> 12) != cls) ? 1.0f : 0.0f;
                float c = __fadd_rn(__fdiv_rn(__fsub_rn(dreg[k], dmin), Dn), lcost);
                unsigned long long p =
                    ((unsigned long long)__float_as_uint(c) << 32) |
                    (unsigned)(jreg[k] & 0xFFF);
                if (p < best) best = p;
            }
        }
#pragma unroll
        for (int o = 16; o > 0; o >>= 1) {
            unsigned long long q = __shfl_xor_sync(0xffffffffu, best, o);
            if (q < best) best = q;
        }
        if (lane == 0) S.rpack[wid] = best;
        __syncthreads();                                   // barrier 2

        unsigned long long v = (lane < NWP) ? S.rpack[lane] : 0xFFFFFFFFFFFFFFFFull;
#pragma unroll
        for (int o = 4; o > 0; o >>= 1) {
            unsigned long long q = __shfl_xor_sync(0xffffffffu, v, o);
            if (q < v) v = q;
        }
        v = __shfl_sync(0xffffffffu, v, 0);
        int sel = (int)(v & 0xFFFull);

        // tail (all threads): swap-remove sel from unvisited (same-value writes)
        {
            int p = S.remap[sel];
            int lastpk = S.items[m - 1];
            S.items[p] = lastpk;
            S.remap[lastpk & 0xFFF] = p;
            m--;
        }
        int ncls = S.slbl[sel];

        // tail (warp 0): cluster decision + state
        if (wid == 0) {
            float cix = S.px[sel], ciy = S.py[sel], ciz = S.pz[sel];
            float dx = __fsub_rn(wcx, cix);
            float dy = __fsub_rn(wcy, ciy);
            float dz = __fsub_rn(wcz, ciz);
            float dn = norm3_xla(dx, dy, dz);
            float cf = (float)cnt;
            float gx = __fdiv_rn((float)sx, cf);
            float gy = __fdiv_rn((float)sy, cf);
            float gz = __fdiv_rn((float)sz, cf);
            float en = norm3_xla(__fsub_rn(gx, cix), __fsub_rn(gy, ciy),
                                 __fsub_rn(gz, ciz));
            float a0 = S.amdxy[cls], a2 = S.amdz[cls], r2 = S.ar2[cls];
            bool newc = (fabsf(dx) > a0) | (fabsf(dy) > a0) | (fabsf(dz) > a2) |
                        angflag | (ncls != cls) | (dn > r2) | (en > r2);
            if (newc) {
                S.ccx[lab] = gx; S.ccy[lab] = gy; S.ccz[lab] = gz;
                S.ccount[lab] = cnt;
                lab += 1;
                sx = (double)cix; sy = (double)ciy; sz = (double)ciz; cnt = 1;
                S.ccls[lab] = ncls;
                mcnt = 0;
            } else {
                sx += (double)cix; sy += (double)ciy; sz += (double)ciz; cnt += 1;
            }
            S.order[mcnt] = sel;  mcnt += 1;   // member list append
            S.sdl[sel] = lab;
        }
        cur = sel; cls = ncls;
    }

    if (wid == 0 && lane == 0) S.bnc = lab;   // num_clusters (exclusive)
    __syncthreads();

    const int nc = S.bnc;

    // ---------------- stable descending sort by count (bitonic, 4096 keys) -----
    unsigned* skey = reinterpret_cast<unsigned*>(S.px);
    for (int i = tid; i < 4096; i += NT) {
        unsigned key = 0;
        if (i < nc) key = ((unsigned)S.ccount[i] << 12) | (4095u - (unsigned)i);
        skey[i] = key;
    }
    for (int i = tid; i < N; i += NT) { S.remap[i] = i; S.keep[i] = 1; }
    __syncthreads();

    for (int k = 2; k <= 4096; k <<= 1) {
        for (int j = k >> 1; j > 0; j >>= 1) {
#pragma unroll
            for (int e = 0; e < 16; ++e) {
                int i = tid + e * NT;
                int ixj = i ^ j;
                if (ixj > i) {
                    unsigned a2 = skey[i], b2 = skey[ixj];
                    bool descBlock = ((i & k) == 0);
                    if (descBlock ? (a2 < b2) : (a2 > b2)) { skey[i] = b2; skey[ixj] = a2; }
                }
            }
            __syncthreads();
        }
    }
    for (int i = tid; i < N; i += NT)
        if (i < nc) S.order[i] = 4095 - (int)(skey[i] & 4095u);
    __syncthreads();

    // ---------------- group order-positions by cluster class ----------
    for (int c = wid; c < 10; c += NWP) {
        int total = 0;
        int limit = (nc + 31) & ~31;
        for (int s = lane; s < limit; s += 32) {
            bool mm = (s < nc) && (S.ccls[S.order[s]] == c);
            unsigned bal = __ballot_sync(0xffffffffu, mm);
            total += __popc(bal);
        }
        if (lane == 0) S.clsCount[c] = total;
    }
    __syncthreads();
    if (tid == 0) {
        int acc = 0;
        for (int c = 0; c < 10; ++c) { S.clsBase[c] = acc; acc += S.clsCount[c]; }
        S.clsBase[10] = acc;
    }
    __syncthreads();
    for (int c = wid; c < 10; c += NWP) {
        int pos = S.clsBase[c];
        int limit = (nc + 31) & ~31;
        for (int s = lane; s < limit; s += 32) {
            bool mm = (s < nc) && (S.ccls[S.order[s]] == c);
            unsigned bal = __ballot_sync(0xffffffffu, mm);
            if (mm) {
                int off = __popc(bal & ((1u << lane) - 1u));
                S.items[pos + off] = s;
            }
            pos += __popc(bal);
        }
    }
    __syncthreads();

    // ---------------- merge: independent per-class sequential chains ----------
    for (int c = wid; c < 10; c += NWP) {
        int base = S.clsBase[c];
        int len  = S.clsBase[c + 1] - base;
        float r2c = S.ar2[c];
        for (int t = 0; t < len; ++t) {
            __syncwarp();
            int ipos = S.items[base + t];
            if (!S.keep[ipos]) continue;
            int idx = S.order[ipos];
            float ax = S.ccx[idx], ay = S.ccy[idx], az = S.ccz[idx];
            for (int s = t + 1 + lane; s < len; s += 32) {
                int jpos = S.items[base + s];
                if (S.keep[jpos]) {
                    int jidx = S.order[jpos];
                    float dd = norm3_xla(__fsub_rn(S.ccx[jidx], ax),
                                         __fsub_rn(S.ccy[jidx], ay),
                                         __fsub_rn(S.ccz[jidx], az));
                    if (dd < r2c) {
                        S.keep[jpos]  = 0;
                        S.remap[jidx] = idx;
                    }
                }
            }
        }
    }
    __syncthreads();

    // ---------------- output (float32) ----------------
    for (int i = tid; i < N; i += NT)
        out[i] = (float)S.remap[S.sdl[i]];
}

extern "C" void kernel_launch(void* const* d_in, const int* in_sizes, int n_in,
                              void* d_out, int out_size)
{
    const float* pts     = nullptr;
    const int*   lbls    = nullptr;
    const float* anchors = nullptr;
    for (int i = 0; i < n_in; ++i) {
        if      (in_sizes[i] == N * 3) pts     = (const float*)d_in[i];
        else if (in_sizes[i] == N)     lbls    = (const int*)  d_in[i];
        else if (in_sizes[i] == 30)    anchors = (const float*)d_in[i];
    }
    if (!pts)     pts     = (const float*)d_in[0];
    if (!lbls)    lbls    = (const int*)  d_in[1];
    if (!anchors) anchors = (const float*)d_in[2];

    float* out = (float*)d_out;
    (void)out_size;

    static bool attr_done = false;
    if (!attr_done) {
        cudaFuncSetAttribute(frustum_cluster_kernel,
                             cudaFuncAttributeMaxDynamicSharedMemorySize,
                             (int)sizeof(Smem));
        attr_done = true;
    }
    dist_kernel<<<N, 256>>>(pts);
    frustum_cluster_kernel<<<1, NT, sizeof(Smem)>>>(pts, lbls, anchors, out);
}